// round 6
// baseline (speedup 1.0000x reference)
#include <cuda_runtime.h>
#include <cuda_fp16.h>
#include <cstdint>

// ----------------------------------------------------------------------------
// BitLinear: y = RMSNorm(x) @ w_q^T * gamma
// R1: harness PTX is baseline sm_103 (no 'a') -> no tcgen05.
// R3: fp16 single pass @773us. R4: 64x64 warp tile @697us.
// R5: frag double-buffer only +12us -> suspect register spill from offset
//     arrays (32 regs) + 64 frag regs on top of 128 acc regs.
// R6: swizzle offsets via XOR identity off(kk)=off(0)^(kk<<5) (saves 24+ regs);
//     one dummy launch to shift ncu capture window onto the GEMM.
// ----------------------------------------------------------------------------

#define DIN   4096
#define DOUT  4096
#define MROWS 8192

__device__ __align__(256) __half g_xn[(size_t)MROWS * DIN];
__device__ __align__(256) __half g_wq[(size_t)DOUT * DIN];

// ---------------------------- PTX helpers -----------------------------------
__device__ __forceinline__ uint32_t smem_u32(const void* p) {
    uint32_t a;
    asm("{ .reg .u64 t; cvta.to.shared.u64 t, %1; cvt.u32.u64 %0, t; }"
        : "=r"(a) : "l"(p));
    return a;
}

__device__ __forceinline__ void cp_async16(uint32_t dst, const void* src) {
    asm volatile("cp.async.cg.shared.global [%0], [%1], 16;"
                 :: "r"(dst), "l"(src));
}

#define CP_COMMIT() asm volatile("cp.async.commit_group;" ::: "memory")

#define LDSM_X4(r0, r1, r2, r3, addr) \
    asm volatile("ldmatrix.sync.aligned.m8n8.x4.shared.b16 {%0,%1,%2,%3}, [%4];" \
                 : "=r"(r0), "=r"(r1), "=r"(r2), "=r"(r3) : "r"(addr))

#define MMA16816(d, a, b0, b1) \
    asm volatile("mma.sync.aligned.m16n8k16.row.col.f32.f16.f16.f32 " \
                 "{%0,%1,%2,%3}, {%4,%5,%6,%7}, {%8,%9}, {%0,%1,%2,%3};" \
                 : "+f"((d)[0]), "+f"((d)[1]), "+f"((d)[2]), "+f"((d)[3]) \
                 : "r"((a)[0]), "r"((a)[1]), "r"((a)[2]), "r"((a)[3]), \
                   "r"(b0), "r"(b1))

// ----------------------------- GEMM config ----------------------------------
constexpr int BM = 128, BN = 256, BK = 64;
constexpr int KTILES = DIN / BK;               // 64
constexpr int STAGES = 4;
constexpr int TILE_A  = BM * BK * 2;           // 16384 B
constexpr int TILE_BB = BN * BK * 2;           // 32768 B
constexpr int STAGE_B = TILE_A + TILE_BB;      // 49152
constexpr int SMEM_SZ = STAGES * STAGE_B;      // 196608

// ------------------------ Kernel 0: dummy (ncu window shift) -----------------
__global__ void dummy_kernel() {}

// ------------------------ Kernel 1: RMSNorm -> fp16 --------------------------
__global__ __launch_bounds__(256) void rmsnorm_kernel(
    const float* __restrict__ x, const float* __restrict__ nw) {
    const int row = blockIdx.x;
    const float4* xr = reinterpret_cast<const float4*>(x) + (size_t)row * (DIN / 4);
    const float4* nw4 = reinterpret_cast<const float4*>(nw);
    const int t = threadIdx.x;

    float4 v[4];
    float ss = 0.f;
#pragma unroll
    for (int i = 0; i < 4; i++) {
        v[i] = xr[t + i * 256];
        ss += v[i].x * v[i].x + v[i].y * v[i].y + v[i].z * v[i].z + v[i].w * v[i].w;
    }
#pragma unroll
    for (int o = 16; o > 0; o >>= 1) ss += __shfl_xor_sync(0xffffffffu, ss, o);

    __shared__ float wss[8];
    __shared__ float s_scale;
    if ((t & 31) == 0) wss[t >> 5] = ss;
    __syncthreads();
    if (t == 0) {
        float tot = 0.f;
#pragma unroll
        for (int i = 0; i < 8; i++) tot += wss[i];
        s_scale = rsqrtf(tot * (1.0f / DIN) + 1e-6f);
    }
    __syncthreads();
    const float sc = s_scale;

    uint2* xo = reinterpret_cast<uint2*>(g_xn + (size_t)row * DIN);
#pragma unroll
    for (int i = 0; i < 4; i++) {
        float4 w = nw4[t + i * 256];
        __half2 h01 = __floats2half2_rn(v[i].x * sc * w.x, v[i].y * sc * w.y);
        __half2 h23 = __floats2half2_rn(v[i].z * sc * w.z, v[i].w * sc * w.w);
        uint2 u;
        u.x = *reinterpret_cast<uint32_t*>(&h01);
        u.y = *reinterpret_cast<uint32_t*>(&h23);
        xo[t + i * 256] = u;
    }
}

// ------------------------ Kernel 2: w_q fp32 -> fp16 --------------------------
__global__ __launch_bounds__(256) void wconv_kernel(const float* __restrict__ w) {
    const size_t gid = (size_t)blockIdx.x * 256 + threadIdx.x;
    const float4* w4 = reinterpret_cast<const float4*>(w);
    uint2* o = reinterpret_cast<uint2*>(g_wq);
#pragma unroll
    for (int i = 0; i < 4; i++) {
        size_t idx = gid + (size_t)i * 1048576;
        float4 v = w4[idx];
        __half2 h01 = __floats2half2_rn(v.x, v.y);
        __half2 h23 = __floats2half2_rn(v.z, v.w);
        uint2 u;
        u.x = *reinterpret_cast<uint32_t*>(&h01);
        u.y = *reinterpret_cast<uint32_t*>(&h23);
        o[idx] = u;
    }
}

// ------------------------ Kernel 3: HMMA GEMM --------------------------------
// 256 threads = 8 warps in a 2(m) x 4(n) grid; warp tile 64x64.
// Fragments double-buffered; ldmatrix offsets derived via XOR identity.
__global__ __launch_bounds__(256, 1)
void bitlinear_gemm_kernel(const float* __restrict__ gamma, float* __restrict__ out) {
    extern __shared__ char smem[];
    const uint32_t sb = smem_u32(smem);
    const int tid = threadIdx.x;
    const int wid = tid >> 5;
    const int lane = tid & 31;
    const int warp_m = wid >> 2;       // 0..1
    const int warp_n = wid & 3;        // 0..3
    const int m0 = blockIdx.y * BM;
    const int n0 = blockIdx.x * BN;

    // ---- per-thread copy geometry (16B chunks; 128B rows, XOR swizzle)
    const int cc = tid & 7;
    const int r0c = tid >> 3;
    const uint32_t so_base = (uint32_t)(r0c * 128 + ((cc ^ (r0c & 7)) << 4));
    const char* gA = (const char*)g_xn + (size_t)m0 * (DIN * 2);
    const char* gB = (const char*)g_wq + (size_t)n0 * (DIN * 2);
    const size_t grow0 = (size_t)r0c * (DIN * 2);

    auto issue_stage = [&](int s, int kt) {
        const uint32_t sdst = sb + (uint32_t)s * STAGE_B;
        const uint32_t koff = (uint32_t)kt * 128 + (uint32_t)cc * 16;
        const char* a = gA + grow0 + koff;
        const char* b = gB + grow0 + koff;
#pragma unroll
        for (int i = 0; i < 4; i++)
            cp_async16(sdst + so_base + i * (32 * 128),
                       a + (size_t)i * (32 * DIN * 2));
#pragma unroll
        for (int i = 0; i < 8; i++)
            cp_async16(sdst + TILE_A + so_base + i * (32 * 128),
                       b + (size_t)i * (32 * DIN * 2));
    };

    // ---- ldmatrix base offsets (kk=0); off(kk) = off0 ^ (kk << 5)
    const int rA0 = warp_m * 64 + (lane & 15);
    const int cgA = lane >> 4;
    const int gB4 = lane >> 3;
    const int rB0 = warp_n * 64 + ((gB4 & 2) << 2) + (lane & 7);
    const int cgB = gB4 & 1;

    uint32_t offA0[4], offB0[4];
#pragma unroll
    for (int mi = 0; mi < 4; mi++) {
        const int r = rA0 + mi * 16;
        offA0[mi] = (uint32_t)(r * 128 + ((cgA ^ (r & 7)) << 4));
    }
#pragma unroll
    for (int p = 0; p < 4; p++) {
        const int r = rB0 + p * 16;
        offB0[p] = (uint32_t)(r * 128 + ((cgB ^ (r & 7)) << 4)) + TILE_A;
    }

    float acc[4][8][4];
#pragma unroll
    for (int mi = 0; mi < 4; mi++)
#pragma unroll
        for (int nj = 0; nj < 8; nj++)
#pragma unroll
            for (int e = 0; e < 4; e++) acc[mi][nj][e] = 0.f;

    uint32_t af[2][4][4], bf[2][4][4];

    auto load_frags = [&](int buf, uint32_t base, int kk) {
        const uint32_t kx = (uint32_t)(kk << 5);
#pragma unroll
        for (int mi = 0; mi < 4; mi++)
            LDSM_X4(af[buf][mi][0], af[buf][mi][1], af[buf][mi][2],
                    af[buf][mi][3], base + (offA0[mi] ^ kx));
#pragma unroll
        for (int p = 0; p < 4; p++)
            LDSM_X4(bf[buf][p][0], bf[buf][p][1], bf[buf][p][2],
                    bf[buf][p][3], base + (offB0[p] ^ kx));
    };

    auto do_mma = [&](int buf) {
#pragma unroll
        for (int mi = 0; mi < 4; mi++)
#pragma unroll
            for (int p = 0; p < 4; p++) {
                MMA16816(acc[mi][2 * p],     af[buf][mi], bf[buf][p][0], bf[buf][p][1]);
                MMA16816(acc[mi][2 * p + 1], af[buf][mi], bf[buf][p][2], bf[buf][p][3]);
            }
    };

    // ---- prologue
#pragma unroll
    for (int s = 0; s < STAGES - 1; s++) { issue_stage(s, s); CP_COMMIT(); }

    // ---- main loop
    for (int kt = 0; kt < KTILES; kt++) {
        asm volatile("cp.async.wait_group 2;" ::: "memory");
        __syncthreads();

        const int nk = kt + STAGES - 1;
        if (nk < KTILES) issue_stage(nk & (STAGES - 1), nk);
        CP_COMMIT();

        const uint32_t base = sb + (uint32_t)(kt & (STAGES - 1)) * STAGE_B;

        load_frags(0, base, 0);
#pragma unroll
        for (int kk = 0; kk < 4; kk++) {
            if (kk < 3) load_frags((kk + 1) & 1, base, kk + 1);
            do_mma(kk & 1);
        }
    }

    // ---- epilogue: *gamma, write f32
    const int col_l = (lane & 3) * 2;
    const float* gptr = gamma + n0 + warp_n * 64;
    float gv0[8], gv1[8];
#pragma unroll
    for (int nj = 0; nj < 8; nj++) {
        gv0[nj] = __ldg(gptr + nj * 8 + col_l);
        gv1[nj] = __ldg(gptr + nj * 8 + col_l + 1);
    }

    const int row_base = m0 + warp_m * 64 + (lane >> 2);
#pragma unroll
    for (int mi = 0; mi < 4; mi++) {
        float* op0 = out + (size_t)(row_base + mi * 16) * DOUT + n0 + warp_n * 64;
        float* op1 = op0 + (size_t)8 * DOUT;
#pragma unroll
        for (int nj = 0; nj < 8; nj++) {
            float2 v0, v1;
            v0.x = acc[mi][nj][0] * gv0[nj];
            v0.y = acc[mi][nj][1] * gv1[nj];
            v1.x = acc[mi][nj][2] * gv0[nj];
            v1.y = acc[mi][nj][3] * gv1[nj];
            *reinterpret_cast<float2*>(op0 + nj * 8 + col_l) = v0;
            *reinterpret_cast<float2*>(op1 + nj * 8 + col_l) = v1;
        }
    }
}

// ------------------------------- launch --------------------------------------
extern "C" void kernel_launch(void* const* d_in, const int* in_sizes, int n_in,
                              void* d_out, int out_size) {
    const float* x     = (const float*)d_in[0];  // [2,4096,4096]
    const float* nw    = (const float*)d_in[1];  // [4096]
    const float* wq    = (const float*)d_in[2];  // [4096,4096]
    const float* gamma = (const float*)d_in[3];  // [4096]
    float* out = (float*)d_out;

    cudaFuncSetAttribute(bitlinear_gemm_kernel,
                         cudaFuncAttributeMaxDynamicSharedMemorySize, SMEM_SZ);

    dummy_kernel<<<1, 32>>>();   // shifts ncu -s5 capture onto the GEMM
    rmsnorm_kernel<<<MROWS, 256>>>(x, nw);
    wconv_kernel<<<4096, 256>>>(wq);
    bitlinear_gemm_kernel<<<dim3(DOUT / BN, MROWS / BM), 256, SMEM_SZ>>>(gamma, out);
}

// round 7
// speedup vs baseline: 1.1101x; 1.1101x over previous
#include <cuda_runtime.h>
#include <cuda_fp16.h>
#include <cstdint>

// ----------------------------------------------------------------------------
// BitLinear: y = RMSNorm(x) @ w_q^T * gamma
// R1: harness PTX is baseline sm_103 (no 'a') -> no tcgen05.
// R3: fp16 single pass @773us. R4/R5/R6: 64x64 warp tile, occ 1 -> 685us.
// R6 profile: GEMM 644us, tensor=70.3%, occ=12.4%, DRAM=4.9%. Latency-bound
//     at 2 warps/SMSP, pipe floor ~455us.
// R7: 2 CTAs/SM (128x128 tile, 3 stages = 96KB smem, launch_bounds(256,2),
//     single-buffered frags, <=128 regs). 4 warps/SMSP covers sync/LDSM gaps.
// ----------------------------------------------------------------------------

#define DIN   4096
#define DOUT  4096
#define MROWS 8192

__device__ __align__(256) __half g_xn[(size_t)MROWS * DIN];
__device__ __align__(256) __half g_wq[(size_t)DOUT * DIN];

// ---------------------------- PTX helpers -----------------------------------
__device__ __forceinline__ uint32_t smem_u32(const void* p) {
    uint32_t a;
    asm("{ .reg .u64 t; cvta.to.shared.u64 t, %1; cvt.u32.u64 %0, t; }"
        : "=r"(a) : "l"(p));
    return a;
}

__device__ __forceinline__ void cp_async16(uint32_t dst, const void* src) {
    asm volatile("cp.async.cg.shared.global [%0], [%1], 16;"
                 :: "r"(dst), "l"(src));
}

#define CP_COMMIT() asm volatile("cp.async.commit_group;" ::: "memory")

#define LDSM_X4(r0, r1, r2, r3, addr) \
    asm volatile("ldmatrix.sync.aligned.m8n8.x4.shared.b16 {%0,%1,%2,%3}, [%4];" \
                 : "=r"(r0), "=r"(r1), "=r"(r2), "=r"(r3) : "r"(addr))

#define MMA16816(d, a, b0, b1) \
    asm volatile("mma.sync.aligned.m16n8k16.row.col.f32.f16.f16.f32 " \
                 "{%0,%1,%2,%3}, {%4,%5,%6,%7}, {%8,%9}, {%0,%1,%2,%3};" \
                 : "+f"((d)[0]), "+f"((d)[1]), "+f"((d)[2]), "+f"((d)[3]) \
                 : "r"((a)[0]), "r"((a)[1]), "r"((a)[2]), "r"((a)[3]), \
                   "r"(b0), "r"(b1))

// ----------------------------- GEMM config ----------------------------------
constexpr int BM = 128, BN = 128, BK = 64;
constexpr int KTILES = DIN / BK;               // 64
constexpr int STAGES = 3;
constexpr int TILE_B  = BM * BK * 2;           // 16384 B per fp16 tile
constexpr int STAGE_B = 2 * TILE_B;            // A + B = 32768
constexpr int SMEM_SZ = STAGES * STAGE_B;      // 98304 (2 CTAs/SM fit)

// ------------------------ Kernel 0: dummy (ncu window shift) -----------------
__global__ void dummy_kernel() {}

// ------------------------ Kernel 1: RMSNorm -> fp16 --------------------------
__global__ __launch_bounds__(256) void rmsnorm_kernel(
    const float* __restrict__ x, const float* __restrict__ nw) {
    const int row = blockIdx.x;
    const float4* xr = reinterpret_cast<const float4*>(x) + (size_t)row * (DIN / 4);
    const float4* nw4 = reinterpret_cast<const float4*>(nw);
    const int t = threadIdx.x;

    float4 v[4];
    float ss = 0.f;
#pragma unroll
    for (int i = 0; i < 4; i++) {
        v[i] = xr[t + i * 256];
        ss += v[i].x * v[i].x + v[i].y * v[i].y + v[i].z * v[i].z + v[i].w * v[i].w;
    }
#pragma unroll
    for (int o = 16; o > 0; o >>= 1) ss += __shfl_xor_sync(0xffffffffu, ss, o);

    __shared__ float wss[8];
    __shared__ float s_scale;
    if ((t & 31) == 0) wss[t >> 5] = ss;
    __syncthreads();
    if (t == 0) {
        float tot = 0.f;
#pragma unroll
        for (int i = 0; i < 8; i++) tot += wss[i];
        s_scale = rsqrtf(tot * (1.0f / DIN) + 1e-6f);
    }
    __syncthreads();
    const float sc = s_scale;

    uint2* xo = reinterpret_cast<uint2*>(g_xn + (size_t)row * DIN);
#pragma unroll
    for (int i = 0; i < 4; i++) {
        float4 w = nw4[t + i * 256];
        __half2 h01 = __floats2half2_rn(v[i].x * sc * w.x, v[i].y * sc * w.y);
        __half2 h23 = __floats2half2_rn(v[i].z * sc * w.z, v[i].w * sc * w.w);
        uint2 u;
        u.x = *reinterpret_cast<uint32_t*>(&h01);
        u.y = *reinterpret_cast<uint32_t*>(&h23);
        xo[t + i * 256] = u;
    }
}

// ------------------------ Kernel 2: w_q fp32 -> fp16 --------------------------
__global__ __launch_bounds__(256) void wconv_kernel(const float* __restrict__ w) {
    const size_t gid = (size_t)blockIdx.x * 256 + threadIdx.x;
    const float4* w4 = reinterpret_cast<const float4*>(w);
    uint2* o = reinterpret_cast<uint2*>(g_wq);
#pragma unroll
    for (int i = 0; i < 4; i++) {
        size_t idx = gid + (size_t)i * 1048576;
        float4 v = w4[idx];
        __half2 h01 = __floats2half2_rn(v.x, v.y);
        __half2 h23 = __floats2half2_rn(v.z, v.w);
        uint2 u;
        u.x = *reinterpret_cast<uint32_t*>(&h01);
        u.y = *reinterpret_cast<uint32_t*>(&h23);
        o[idx] = u;
    }
}

// ------------------------ Kernel 3: HMMA GEMM --------------------------------
// 256 threads = 8 warps in a 4(m) x 2(n) grid; warp tile 32x64; 2 CTAs/SM.
__global__ __launch_bounds__(256, 2)
void bitlinear_gemm_kernel(const float* __restrict__ gamma, float* __restrict__ out) {
    extern __shared__ char smem[];
    const uint32_t sb = smem_u32(smem);
    const int tid = threadIdx.x;
    const int wid = tid >> 5;
    const int lane = tid & 31;
    const int warp_m = wid >> 1;       // 0..3
    const int warp_n = wid & 1;        // 0..1
    const int m0 = blockIdx.y * BM;
    const int n0 = blockIdx.x * BN;

    // ---- per-thread copy geometry (16B chunks; 128B rows, XOR swizzle)
    const int cc = tid & 7;
    const int r0c = tid >> 3;
    const uint32_t so_base = (uint32_t)(r0c * 128 + ((cc ^ (r0c & 7)) << 4));
    const char* gA = (const char*)g_xn + (size_t)m0 * (DIN * 2);
    const char* gB = (const char*)g_wq + (size_t)n0 * (DIN * 2);
    const size_t grow0 = (size_t)r0c * (DIN * 2);

    auto issue_stage = [&](int s, int kt) {
        const uint32_t sdst = sb + (uint32_t)s * STAGE_B;
        const uint32_t koff = (uint32_t)kt * 128 + (uint32_t)cc * 16;
        const char* a = gA + grow0 + koff;
        const char* b = gB + grow0 + koff;
#pragma unroll
        for (int i = 0; i < 4; i++)
            cp_async16(sdst + so_base + i * (32 * 128),
                       a + (size_t)i * (32 * DIN * 2));
#pragma unroll
        for (int i = 0; i < 4; i++)
            cp_async16(sdst + TILE_B + so_base + i * (32 * 128),
                       b + (size_t)i * (32 * DIN * 2));
    };

    // ---- ldmatrix base offsets (kk=0); off(kk) = off0 ^ (kk << 5)
    const int rA0 = warp_m * 32 + (lane & 15);
    const int cgA = lane >> 4;
    const int gB4 = lane >> 3;
    const int rB0 = warp_n * 64 + ((gB4 & 2) << 2) + (lane & 7);
    const int cgB = gB4 & 1;

    uint32_t offA0[2], offB0[4];
#pragma unroll
    for (int mi = 0; mi < 2; mi++) {
        const int r = rA0 + mi * 16;
        offA0[mi] = (uint32_t)(r * 128 + ((cgA ^ (r & 7)) << 4));
    }
#pragma unroll
    for (int p = 0; p < 4; p++) {
        const int r = rB0 + p * 16;
        offB0[p] = (uint32_t)(r * 128 + ((cgB ^ (r & 7)) << 4)) + TILE_B;
    }

    float acc[2][8][4];
#pragma unroll
    for (int mi = 0; mi < 2; mi++)
#pragma unroll
        for (int nj = 0; nj < 8; nj++)
#pragma unroll
            for (int e = 0; e < 4; e++) acc[mi][nj][e] = 0.f;

    // ---- prologue: fill 2 stages
#pragma unroll
    for (int s = 0; s < STAGES - 1; s++) { issue_stage(s, s); CP_COMMIT(); }

    // ---- main loop
    int stage = 0;
    for (int kt = 0; kt < KTILES; kt++) {
        asm volatile("cp.async.wait_group 1;" ::: "memory");
        __syncthreads();

        const int nk = kt + STAGES - 1;
        if (nk < KTILES) {
            int ns = stage + (STAGES - 1);
            if (ns >= STAGES) ns -= STAGES;
            issue_stage(ns, nk);
        }
        CP_COMMIT();

        const uint32_t base = sb + (uint32_t)stage * STAGE_B;

#pragma unroll
        for (int kk = 0; kk < 4; kk++) {
            const uint32_t kx = (uint32_t)(kk << 5);
            uint32_t af[2][4], bf[4][4];
#pragma unroll
            for (int mi = 0; mi < 2; mi++)
                LDSM_X4(af[mi][0], af[mi][1], af[mi][2], af[mi][3],
                        base + (offA0[mi] ^ kx));
#pragma unroll
            for (int p = 0; p < 4; p++)
                LDSM_X4(bf[p][0], bf[p][1], bf[p][2], bf[p][3],
                        base + (offB0[p] ^ kx));
#pragma unroll
            for (int mi = 0; mi < 2; mi++)
#pragma unroll
                for (int p = 0; p < 4; p++) {
                    MMA16816(acc[mi][2 * p],     af[mi], bf[p][0], bf[p][1]);
                    MMA16816(acc[mi][2 * p + 1], af[mi], bf[p][2], bf[p][3]);
                }
        }
        if (++stage == STAGES) stage = 0;
    }

    // ---- epilogue: *gamma, write f32
    const int col_l = (lane & 3) * 2;
    const float* gptr = gamma + n0 + warp_n * 64;
    float gv0[8], gv1[8];
#pragma unroll
    for (int nj = 0; nj < 8; nj++) {
        gv0[nj] = __ldg(gptr + nj * 8 + col_l);
        gv1[nj] = __ldg(gptr + nj * 8 + col_l + 1);
    }

    const int row_base = m0 + warp_m * 32 + (lane >> 2);
#pragma unroll
    for (int mi = 0; mi < 2; mi++) {
        float* op0 = out + (size_t)(row_base + mi * 16) * DOUT + n0 + warp_n * 64;
        float* op1 = op0 + (size_t)8 * DOUT;
#pragma unroll
        for (int nj = 0; nj < 8; nj++) {
            float2 v0, v1;
            v0.x = acc[mi][nj][0] * gv0[nj];
            v0.y = acc[mi][nj][1] * gv1[nj];
            v1.x = acc[mi][nj][2] * gv0[nj];
            v1.y = acc[mi][nj][3] * gv1[nj];
            *reinterpret_cast<float2*>(op0 + nj * 8 + col_l) = v0;
            *reinterpret_cast<float2*>(op1 + nj * 8 + col_l) = v1;
        }
    }
}

// ------------------------------- launch --------------------------------------
extern "C" void kernel_launch(void* const* d_in, const int* in_sizes, int n_in,
                              void* d_out, int out_size) {
    const float* x     = (const float*)d_in[0];  // [2,4096,4096]
    const float* nw    = (const float*)d_in[1];  // [4096]
    const float* wq    = (const float*)d_in[2];  // [4096,4096]
    const float* gamma = (const float*)d_in[3];  // [4096]
    float* out = (float*)d_out;

    cudaFuncSetAttribute(bitlinear_gemm_kernel,
                         cudaFuncAttributeMaxDynamicSharedMemorySize, SMEM_SZ);

    dummy_kernel<<<1, 32>>>();   // keeps ncu -s5 capture on the GEMM
    rmsnorm_kernel<<<MROWS, 256>>>(x, nw);
    wconv_kernel<<<4096, 256>>>(wq);
    bitlinear_gemm_kernel<<<dim3(DOUT / BN, MROWS / BM), 256, SMEM_SZ>>>(gamma, out);
}

// round 8
// speedup vs baseline: 1.1567x; 1.0420x over previous
#include <cuda_runtime.h>
#include <cuda_fp16.h>
#include <cstdint>

// ----------------------------------------------------------------------------
// BitLinear: y = RMSNorm(x) @ w_q^T * gamma
// R1: harness PTX is baseline sm_103 (no 'a') -> no tcgen05.
// R3: fp16 single pass @773us. R6: occ1 64x64 tile, tensor=70.3% @685us.
// R7: occ2 (128x128, 3 stages, 126 regs): tensor=78.8%, GEMM 575us, 621 total.
//     HMMA rt~8/SMSP -> floor ~477us GEMM. Residual = correlated sync/LDSM
//     bubbles (all warps sync per kt, then dependent LDSM->HMMA chains).
// R8: fragment software-pipeline at occ2: all LDSM one kk ahead (double-buffered
//     frags), barrier moved after kk3 HMMAs, cross-kt kk0 prefetch post-sync.
// ----------------------------------------------------------------------------

#define DIN   4096
#define DOUT  4096
#define MROWS 8192

__device__ __align__(256) __half g_xn[(size_t)MROWS * DIN];
__device__ __align__(256) __half g_wq[(size_t)DOUT * DIN];

// ---------------------------- PTX helpers -----------------------------------
__device__ __forceinline__ uint32_t smem_u32(const void* p) {
    uint32_t a;
    asm("{ .reg .u64 t; cvta.to.shared.u64 t, %1; cvt.u32.u64 %0, t; }"
        : "=r"(a) : "l"(p));
    return a;
}

__device__ __forceinline__ void cp_async16(uint32_t dst, const void* src) {
    asm volatile("cp.async.cg.shared.global [%0], [%1], 16;"
                 :: "r"(dst), "l"(src));
}

#define CP_COMMIT() asm volatile("cp.async.commit_group;" ::: "memory")

#define LDSM_X4(r0, r1, r2, r3, addr) \
    asm volatile("ldmatrix.sync.aligned.m8n8.x4.shared.b16 {%0,%1,%2,%3}, [%4];" \
                 : "=r"(r0), "=r"(r1), "=r"(r2), "=r"(r3) : "r"(addr))

#define MMA16816(d, a, b0, b1) \
    asm volatile("mma.sync.aligned.m16n8k16.row.col.f32.f16.f16.f32 " \
                 "{%0,%1,%2,%3}, {%4,%5,%6,%7}, {%8,%9}, {%0,%1,%2,%3};" \
                 : "+f"((d)[0]), "+f"((d)[1]), "+f"((d)[2]), "+f"((d)[3]) \
                 : "r"((a)[0]), "r"((a)[1]), "r"((a)[2]), "r"((a)[3]), \
                   "r"(b0), "r"(b1))

// ----------------------------- GEMM config ----------------------------------
constexpr int BM = 128, BN = 128, BK = 64;
constexpr int KTILES = DIN / BK;               // 64
constexpr int STAGES = 3;
constexpr int TILE_B  = BM * BK * 2;           // 16384 B per fp16 tile
constexpr int STAGE_B = 2 * TILE_B;            // A + B = 32768
constexpr int SMEM_SZ = STAGES * STAGE_B;      // 98304 (2 CTAs/SM fit)

// ------------------------ Kernel 0: dummy (ncu window shift) -----------------
__global__ void dummy_kernel() {}

// ------------------------ Kernel 1: RMSNorm -> fp16 --------------------------
__global__ __launch_bounds__(256) void rmsnorm_kernel(
    const float* __restrict__ x, const float* __restrict__ nw) {
    const int row = blockIdx.x;
    const float4* xr = reinterpret_cast<const float4*>(x) + (size_t)row * (DIN / 4);
    const float4* nw4 = reinterpret_cast<const float4*>(nw);
    const int t = threadIdx.x;

    float4 v[4];
    float ss = 0.f;
#pragma unroll
    for (int i = 0; i < 4; i++) {
        v[i] = xr[t + i * 256];
        ss += v[i].x * v[i].x + v[i].y * v[i].y + v[i].z * v[i].z + v[i].w * v[i].w;
    }
#pragma unroll
    for (int o = 16; o > 0; o >>= 1) ss += __shfl_xor_sync(0xffffffffu, ss, o);

    __shared__ float wss[8];
    __shared__ float s_scale;
    if ((t & 31) == 0) wss[t >> 5] = ss;
    __syncthreads();
    if (t == 0) {
        float tot = 0.f;
#pragma unroll
        for (int i = 0; i < 8; i++) tot += wss[i];
        s_scale = rsqrtf(tot * (1.0f / DIN) + 1e-6f);
    }
    __syncthreads();
    const float sc = s_scale;

    uint2* xo = reinterpret_cast<uint2*>(g_xn + (size_t)row * DIN);
#pragma unroll
    for (int i = 0; i < 4; i++) {
        float4 w = nw4[t + i * 256];
        __half2 h01 = __floats2half2_rn(v[i].x * sc * w.x, v[i].y * sc * w.y);
        __half2 h23 = __floats2half2_rn(v[i].z * sc * w.z, v[i].w * sc * w.w);
        uint2 u;
        u.x = *reinterpret_cast<uint32_t*>(&h01);
        u.y = *reinterpret_cast<uint32_t*>(&h23);
        xo[t + i * 256] = u;
    }
}

// ------------------------ Kernel 2: w_q fp32 -> fp16 --------------------------
__global__ __launch_bounds__(256) void wconv_kernel(const float* __restrict__ w) {
    const size_t gid = (size_t)blockIdx.x * 256 + threadIdx.x;
    const float4* w4 = reinterpret_cast<const float4*>(w);
    uint2* o = reinterpret_cast<uint2*>(g_wq);
#pragma unroll
    for (int i = 0; i < 4; i++) {
        size_t idx = gid + (size_t)i * 1048576;
        float4 v = w4[idx];
        __half2 h01 = __floats2half2_rn(v.x, v.y);
        __half2 h23 = __floats2half2_rn(v.z, v.w);
        uint2 u;
        u.x = *reinterpret_cast<uint32_t*>(&h01);
        u.y = *reinterpret_cast<uint32_t*>(&h23);
        o[idx] = u;
    }
}

// ------------------------ Kernel 3: HMMA GEMM --------------------------------
// 256 threads = 8 warps, 4(m) x 2(n), warp tile 32x64; 2 CTAs/SM.
// All fragments loaded one kk-step ahead; barrier after kk3 HMMAs.
__global__ __launch_bounds__(256, 2)
void bitlinear_gemm_kernel(const float* __restrict__ gamma, float* __restrict__ out) {
    extern __shared__ char smem[];
    const uint32_t sb = smem_u32(smem);
    const int tid = threadIdx.x;
    const int wid = tid >> 5;
    const int lane = tid & 31;
    const int warp_m = wid >> 1;       // 0..3
    const int warp_n = wid & 1;        // 0..1
    const int m0 = blockIdx.y * BM;
    const int n0 = blockIdx.x * BN;

    // ---- per-thread copy geometry (16B chunks; 128B rows, XOR swizzle)
    const int cc = tid & 7;
    const int r0c = tid >> 3;
    const uint32_t so_base = (uint32_t)(r0c * 128 + ((cc ^ (r0c & 7)) << 4));
    const char* gA = (const char*)g_xn + (size_t)(m0 + r0c) * (DIN * 2) + cc * 16;
    const char* gB = (const char*)g_wq + (size_t)(n0 + r0c) * (DIN * 2) + cc * 16;

    auto issue_stage = [&](int s, int kt) {
        const uint32_t sdst = sb + (uint32_t)s * STAGE_B + so_base;
        const uint32_t koff = (uint32_t)kt * 128;
#pragma unroll
        for (int i = 0; i < 4; i++)
            cp_async16(sdst + i * (32 * 128),
                       gA + koff + (size_t)i * (32 * DIN * 2));
#pragma unroll
        for (int i = 0; i < 4; i++)
            cp_async16(sdst + TILE_B + i * (32 * 128),
                       gB + koff + (size_t)i * (32 * DIN * 2));
    };

    // ---- ldmatrix base offsets (kk=0); off(kk) = off0 ^ (kk << 5)
    const int rA0 = warp_m * 32 + (lane & 15);
    const int cgA = lane >> 4;
    const int gB4 = lane >> 3;
    const int rB0 = warp_n * 64 + ((gB4 & 2) << 2) + (lane & 7);
    const int cgB = gB4 & 1;

    uint32_t offA0[2], offB0[4];
#pragma unroll
    for (int mi = 0; mi < 2; mi++) {
        const int r = rA0 + mi * 16;
        offA0[mi] = (uint32_t)(r * 128 + ((cgA ^ (r & 7)) << 4));
    }
#pragma unroll
    for (int p = 0; p < 4; p++) {
        const int r = rB0 + p * 16;
        offB0[p] = (uint32_t)(r * 128 + ((cgB ^ (r & 7)) << 4)) + TILE_B;
    }

    float acc[2][8][4];
#pragma unroll
    for (int mi = 0; mi < 2; mi++)
#pragma unroll
        for (int nj = 0; nj < 8; nj++)
#pragma unroll
            for (int e = 0; e < 4; e++) acc[mi][nj][e] = 0.f;

    uint32_t af[2][2][4], bf[2][4][4];   // [buf][frag][reg]

    auto load_frags = [&](int buf, uint32_t base, int kk) {
        const uint32_t kx = (uint32_t)(kk << 5);
#pragma unroll
        for (int mi = 0; mi < 2; mi++)
            LDSM_X4(af[buf][mi][0], af[buf][mi][1], af[buf][mi][2],
                    af[buf][mi][3], base + (offA0[mi] ^ kx));
#pragma unroll
        for (int p = 0; p < 4; p++)
            LDSM_X4(bf[buf][p][0], bf[buf][p][1], bf[buf][p][2],
                    bf[buf][p][3], base + (offB0[p] ^ kx));
    };

    auto do_mma = [&](int buf) {
#pragma unroll
        for (int mi = 0; mi < 2; mi++)
#pragma unroll
            for (int p = 0; p < 4; p++) {
                MMA16816(acc[mi][2 * p],     af[buf][mi], bf[buf][p][0], bf[buf][p][1]);
                MMA16816(acc[mi][2 * p + 1], af[buf][mi], bf[buf][p][2], bf[buf][p][3]);
            }
    };

    // ---- prologue: fill 2 stages, publish stage 0, prefetch its kk0 frags
    issue_stage(0, 0); CP_COMMIT();
    issue_stage(1, 1); CP_COMMIT();
    asm volatile("cp.async.wait_group 1;" ::: "memory");   // stage 0 ready
    __syncthreads();                                        // publish stage 0
    load_frags(0, sb, 0);

    // ---- main loop: frags always one kk ahead; barrier after kk3 HMMAs
    int stage = 0;
    for (int kt = 0; kt < KTILES; kt++) {
        const uint32_t base = sb + (uint32_t)stage * STAGE_B;

        // issue stage kt+2 into slot (stage+2)%3 (consumers done pre-barrier)
        if (kt + 2 < KTILES) {
            int ns = stage + 2; if (ns >= STAGES) ns -= STAGES;
            issue_stage(ns, kt + 2);
        }
        CP_COMMIT();

#pragma unroll
        for (int kk = 0; kk < 3; kk++) {
            load_frags((kk + 1) & 1, base, kk + 1);
            do_mma(kk & 1);
        }
        do_mma(1);   // kk=3 (frags loaded at kk=2 into buf 1)

        // stage kt+1 ready (pending <=1 leaves only kt+2's group)
        asm volatile("cp.async.wait_group 1;" ::: "memory");
        __syncthreads();

        int nstage = stage + 1; if (nstage >= STAGES) nstage -= STAGES;
        if (kt + 1 < KTILES)
            load_frags(0, sb + (uint32_t)nstage * STAGE_B, 0);
        stage = nstage;
    }

    // ---- epilogue: *gamma, write f32
    const int col_l = (lane & 3) * 2;
    const float* gptr = gamma + n0 + warp_n * 64;
    float gv0[8], gv1[8];
#pragma unroll
    for (int nj = 0; nj < 8; nj++) {
        gv0[nj] = __ldg(gptr + nj * 8 + col_l);
        gv1[nj] = __ldg(gptr + nj * 8 + col_l + 1);
    }

    const int row_base = m0 + warp_m * 32 + (lane >> 2);
#pragma unroll
    for (int mi = 0; mi < 2; mi++) {
        float* op0 = out + (size_t)(row_base + mi * 16) * DOUT + n0 + warp_n * 64;
        float* op1 = op0 + (size_t)8 * DOUT;
#pragma unroll
        for (int nj = 0; nj < 8; nj++) {
            float2 v0, v1;
            v0.x = acc[mi][nj][0] * gv0[nj];
            v0.y = acc[mi][nj][1] * gv1[nj];
            v1.x = acc[mi][nj][2] * gv0[nj];
            v1.y = acc[mi][nj][3] * gv1[nj];
            *reinterpret_cast<float2*>(op0 + nj * 8 + col_l) = v0;
            *reinterpret_cast<float2*>(op1 + nj * 8 + col_l) = v1;
        }
    }
}

// ------------------------------- launch --------------------------------------
extern "C" void kernel_launch(void* const* d_in, const int* in_sizes, int n_in,
                              void* d_out, int out_size) {
    const float* x     = (const float*)d_in[0];  // [2,4096,4096]
    const float* nw    = (const float*)d_in[1];  // [4096]
    const float* wq    = (const float*)d_in[2];  // [4096,4096]
    const float* gamma = (const float*)d_in[3];  // [4096]
    float* out = (float*)d_out;

    cudaFuncSetAttribute(bitlinear_gemm_kernel,
                         cudaFuncAttributeMaxDynamicSharedMemorySize, SMEM_SZ);

    dummy_kernel<<<1, 32>>>();   // keeps ncu -s5 capture on the GEMM
    rmsnorm_kernel<<<MROWS, 256>>>(x, nw);
    wconv_kernel<<<4096, 256>>>(wq);
    bitlinear_gemm_kernel<<<dim3(DOUT / BN, MROWS / BM), 256, SMEM_SZ>>>(gamma, out);
}

// round 9
// speedup vs baseline: 1.2464x; 1.0775x over previous
#include <cuda_runtime.h>
#include <cuda_fp16.h>
#include <cstdint>

// ----------------------------------------------------------------------------
// BitLinear: y = RMSNorm(x) @ w_q^T * gamma
// R1: harness PTX is baseline sm_103 (no 'a') -> no tcgen05.
// R7: occ2 128x128/8warps: tensor 78.8% @621. R8: frag pipeline: 82.6% @596,
//     L1=72.5% -> smem crossbar co-saturated (LDSM 192B/HMMA + STS ~ HMMA cyc).
// R9: 64x64 warp tiles at occ2 via 128-thread CTAs (4 warps, 2m x 2n):
//     LDSM bytes/HMMA -33%; 2 warps/SMSP now from INDEPENDENT CTAs
//     (decorrelated barriers). Keep cross-kt fragment pipeline.
// ----------------------------------------------------------------------------

#define DIN   4096
#define DOUT  4096
#define MROWS 8192

__device__ __align__(256) __half g_xn[(size_t)MROWS * DIN];
__device__ __align__(256) __half g_wq[(size_t)DOUT * DIN];

// ---------------------------- PTX helpers -----------------------------------
__device__ __forceinline__ uint32_t smem_u32(const void* p) {
    uint32_t a;
    asm("{ .reg .u64 t; cvta.to.shared.u64 t, %1; cvt.u32.u64 %0, t; }"
        : "=r"(a) : "l"(p));
    return a;
}

__device__ __forceinline__ void cp_async16(uint32_t dst, const void* src) {
    asm volatile("cp.async.cg.shared.global [%0], [%1], 16;"
                 :: "r"(dst), "l"(src));
}

#define CP_COMMIT() asm volatile("cp.async.commit_group;" ::: "memory")

#define LDSM_X4(r0, r1, r2, r3, addr) \
    asm volatile("ldmatrix.sync.aligned.m8n8.x4.shared.b16 {%0,%1,%2,%3}, [%4];" \
                 : "=r"(r0), "=r"(r1), "=r"(r2), "=r"(r3) : "r"(addr))

#define MMA16816(d, a, b0, b1) \
    asm volatile("mma.sync.aligned.m16n8k16.row.col.f32.f16.f16.f32 " \
                 "{%0,%1,%2,%3}, {%4,%5,%6,%7}, {%8,%9}, {%0,%1,%2,%3};" \
                 : "+f"((d)[0]), "+f"((d)[1]), "+f"((d)[2]), "+f"((d)[3]) \
                 : "r"((a)[0]), "r"((a)[1]), "r"((a)[2]), "r"((a)[3]), \
                   "r"(b0), "r"(b1))

// ----------------------------- GEMM config ----------------------------------
constexpr int BM = 128, BN = 128, BK = 64;
constexpr int KTILES = DIN / BK;               // 64
constexpr int STAGES = 3;
constexpr int TILE_B  = BM * BK * 2;           // 16384 B per fp16 tile
constexpr int STAGE_B = 2 * TILE_B;            // A + B = 32768
constexpr int SMEM_SZ = STAGES * STAGE_B;      // 98304 (2 CTAs/SM: 192KB)
constexpr int NTHREADS = 128;                  // 4 warps, warp tile 64x64

// ------------------------ Kernel 0: dummy (ncu window shift) -----------------
__global__ void dummy_kernel() {}

// ------------------------ Kernel 1: RMSNorm -> fp16 --------------------------
__global__ __launch_bounds__(256) void rmsnorm_kernel(
    const float* __restrict__ x, const float* __restrict__ nw) {
    const int row = blockIdx.x;
    const float4* xr = reinterpret_cast<const float4*>(x) + (size_t)row * (DIN / 4);
    const float4* nw4 = reinterpret_cast<const float4*>(nw);
    const int t = threadIdx.x;

    float4 v[4];
    float ss = 0.f;
#pragma unroll
    for (int i = 0; i < 4; i++) {
        v[i] = xr[t + i * 256];
        ss += v[i].x * v[i].x + v[i].y * v[i].y + v[i].z * v[i].z + v[i].w * v[i].w;
    }
#pragma unroll
    for (int o = 16; o > 0; o >>= 1) ss += __shfl_xor_sync(0xffffffffu, ss, o);

    __shared__ float wss[8];
    __shared__ float s_scale;
    if ((t & 31) == 0) wss[t >> 5] = ss;
    __syncthreads();
    if (t == 0) {
        float tot = 0.f;
#pragma unroll
        for (int i = 0; i < 8; i++) tot += wss[i];
        s_scale = rsqrtf(tot * (1.0f / DIN) + 1e-6f);
    }
    __syncthreads();
    const float sc = s_scale;

    uint2* xo = reinterpret_cast<uint2*>(g_xn + (size_t)row * DIN);
#pragma unroll
    for (int i = 0; i < 4; i++) {
        float4 w = nw4[t + i * 256];
        __half2 h01 = __floats2half2_rn(v[i].x * sc * w.x, v[i].y * sc * w.y);
        __half2 h23 = __floats2half2_rn(v[i].z * sc * w.z, v[i].w * sc * w.w);
        uint2 u;
        u.x = *reinterpret_cast<uint32_t*>(&h01);
        u.y = *reinterpret_cast<uint32_t*>(&h23);
        xo[t + i * 256] = u;
    }
}

// ------------------------ Kernel 2: w_q fp32 -> fp16 --------------------------
__global__ __launch_bounds__(256) void wconv_kernel(const float* __restrict__ w) {
    const size_t gid = (size_t)blockIdx.x * 256 + threadIdx.x;
    const float4* w4 = reinterpret_cast<const float4*>(w);
    uint2* o = reinterpret_cast<uint2*>(g_wq);
#pragma unroll
    for (int i = 0; i < 4; i++) {
        size_t idx = gid + (size_t)i * 1048576;
        float4 v = w4[idx];
        __half2 h01 = __floats2half2_rn(v.x, v.y);
        __half2 h23 = __floats2half2_rn(v.z, v.w);
        uint2 u;
        u.x = *reinterpret_cast<uint32_t*>(&h01);
        u.y = *reinterpret_cast<uint32_t*>(&h23);
        o[idx] = u;
    }
}

// ------------------------ Kernel 3: HMMA GEMM --------------------------------
// 128 threads = 4 warps, 2(m) x 2(n), warp tile 64x64; 2 CTAs/SM.
// All fragments one kk-step ahead; barrier after kk3 HMMAs.
__global__ __launch_bounds__(NTHREADS, 2)
void bitlinear_gemm_kernel(const float* __restrict__ gamma, float* __restrict__ out) {
    extern __shared__ char smem[];
    const uint32_t sb = smem_u32(smem);
    const int tid = threadIdx.x;
    const int wid = tid >> 5;
    const int lane = tid & 31;
    const int warp_m = wid >> 1;       // 0..1
    const int warp_n = wid & 1;        // 0..1
    const int m0 = blockIdx.y * BM;
    const int n0 = blockIdx.x * BN;

    // ---- per-thread copy geometry: 1024 chunks/tile, 128 thr -> 8 each
    const int cc = tid & 7;
    const int r0c = tid >> 3;          // 0..15; r&7 invariant under +16
    const uint32_t so_base = (uint32_t)(r0c * 128 + ((cc ^ (r0c & 7)) << 4));
    const char* gA = (const char*)g_xn + (size_t)(m0 + r0c) * (DIN * 2) + cc * 16;
    const char* gB = (const char*)g_wq + (size_t)(n0 + r0c) * (DIN * 2) + cc * 16;

    auto issue_stage = [&](int s, int kt) {
        const uint32_t sdst = sb + (uint32_t)s * STAGE_B + so_base;
        const uint32_t koff = (uint32_t)kt * 128;
#pragma unroll
        for (int i = 0; i < 8; i++)
            cp_async16(sdst + i * (16 * 128),
                       gA + koff + (size_t)i * (16 * DIN * 2));
#pragma unroll
        for (int i = 0; i < 8; i++)
            cp_async16(sdst + TILE_B + i * (16 * 128),
                       gB + koff + (size_t)i * (16 * DIN * 2));
    };

    // ---- ldmatrix base offsets (kk=0); off(kk) = off0 ^ (kk << 5)
    const int rA0 = warp_m * 64 + (lane & 15);
    const int cgA = lane >> 4;
    const int gB4 = lane >> 3;
    const int rB0 = warp_n * 64 + ((gB4 & 2) << 2) + (lane & 7);
    const int cgB = gB4 & 1;

    uint32_t offA0[4], offB0[4];
#pragma unroll
    for (int mi = 0; mi < 4; mi++) {
        const int r = rA0 + mi * 16;
        offA0[mi] = (uint32_t)(r * 128 + ((cgA ^ (r & 7)) << 4));
    }
#pragma unroll
    for (int p = 0; p < 4; p++) {
        const int r = rB0 + p * 16;
        offB0[p] = (uint32_t)(r * 128 + ((cgB ^ (r & 7)) << 4)) + TILE_B;
    }

    float acc[4][8][4];
#pragma unroll
    for (int mi = 0; mi < 4; mi++)
#pragma unroll
        for (int nj = 0; nj < 8; nj++)
#pragma unroll
            for (int e = 0; e < 4; e++) acc[mi][nj][e] = 0.f;

    uint32_t af[2][4][4], bf[2][4][4];   // [buf][frag][reg]

    auto load_frags = [&](int buf, uint32_t base, int kk) {
        const uint32_t kx = (uint32_t)(kk << 5);
#pragma unroll
        for (int mi = 0; mi < 4; mi++)
            LDSM_X4(af[buf][mi][0], af[buf][mi][1], af[buf][mi][2],
                    af[buf][mi][3], base + (offA0[mi] ^ kx));
#pragma unroll
        for (int p = 0; p < 4; p++)
            LDSM_X4(bf[buf][p][0], bf[buf][p][1], bf[buf][p][2],
                    bf[buf][p][3], base + (offB0[p] ^ kx));
    };

    auto do_mma = [&](int buf) {
#pragma unroll
        for (int mi = 0; mi < 4; mi++)
#pragma unroll
            for (int p = 0; p < 4; p++) {
                MMA16816(acc[mi][2 * p],     af[buf][mi], bf[buf][p][0], bf[buf][p][1]);
                MMA16816(acc[mi][2 * p + 1], af[buf][mi], bf[buf][p][2], bf[buf][p][3]);
            }
    };

    // ---- prologue: fill 2 stages, publish stage 0, prefetch its kk0 frags
    issue_stage(0, 0); CP_COMMIT();
    issue_stage(1, 1); CP_COMMIT();
    asm volatile("cp.async.wait_group 1;" ::: "memory");
    __syncthreads();
    load_frags(0, sb, 0);

    // ---- main loop: frags always one kk ahead; barrier after kk3 HMMAs
    int stage = 0;
    for (int kt = 0; kt < KTILES; kt++) {
        const uint32_t base = sb + (uint32_t)stage * STAGE_B;

        if (kt + 2 < KTILES) {
            int ns = stage + 2; if (ns >= STAGES) ns -= STAGES;
            issue_stage(ns, kt + 2);
        }
        CP_COMMIT();

#pragma unroll
        for (int kk = 0; kk < 3; kk++) {
            load_frags((kk + 1) & 1, base, kk + 1);
            do_mma(kk & 1);
        }
        do_mma(1);   // kk=3

        asm volatile("cp.async.wait_group 1;" ::: "memory");
        __syncthreads();

        int nstage = stage + 1; if (nstage >= STAGES) nstage -= STAGES;
        if (kt + 1 < KTILES)
            load_frags(0, sb + (uint32_t)nstage * STAGE_B, 0);
        stage = nstage;
    }

    // ---- epilogue: *gamma, write f32
    const int col_l = (lane & 3) * 2;
    const float* gptr = gamma + n0 + warp_n * 64;
    float gv0[8], gv1[8];
#pragma unroll
    for (int nj = 0; nj < 8; nj++) {
        gv0[nj] = __ldg(gptr + nj * 8 + col_l);
        gv1[nj] = __ldg(gptr + nj * 8 + col_l + 1);
    }

    const int row_base = m0 + warp_m * 64 + (lane >> 2);
#pragma unroll
    for (int mi = 0; mi < 4; mi++) {
        float* op0 = out + (size_t)(row_base + mi * 16) * DOUT + n0 + warp_n * 64;
        float* op1 = op0 + (size_t)8 * DOUT;
#pragma unroll
        for (int nj = 0; nj < 8; nj++) {
            float2 v0, v1;
            v0.x = acc[mi][nj][0] * gv0[nj];
            v0.y = acc[mi][nj][1] * gv1[nj];
            v1.x = acc[mi][nj][2] * gv0[nj];
            v1.y = acc[mi][nj][3] * gv1[nj];
            *reinterpret_cast<float2*>(op0 + nj * 8 + col_l) = v0;
            *reinterpret_cast<float2*>(op1 + nj * 8 + col_l) = v1;
        }
    }
}

// ------------------------------- launch --------------------------------------
extern "C" void kernel_launch(void* const* d_in, const int* in_sizes, int n_in,
                              void* d_out, int out_size) {
    const float* x     = (const float*)d_in[0];  // [2,4096,4096]
    const float* nw    = (const float*)d_in[1];  // [4096]
    const float* wq    = (const float*)d_in[2];  // [4096,4096]
    const float* gamma = (const float*)d_in[3];  // [4096]
    float* out = (float*)d_out;

    cudaFuncSetAttribute(bitlinear_gemm_kernel,
                         cudaFuncAttributeMaxDynamicSharedMemorySize, SMEM_SZ);

    dummy_kernel<<<1, 32>>>();   // keeps ncu -s5 capture on the GEMM
    rmsnorm_kernel<<<MROWS, 256>>>(x, nw);
    wconv_kernel<<<4096, 256>>>(wq);
    bitlinear_gemm_kernel<<<dim3(DOUT / BN, MROWS / BM), NTHREADS, SMEM_SZ>>>(gamma, out);
}